// round 13
// baseline (speedup 1.0000x reference)
#include <cuda_runtime.h>
#include <cuda_bf16.h>
#include <stdint.h>

#define D_DIM   256
#define TM      128
#define TN      128
#define KC      32
#define NCH     (D_DIM / KC)
#define K_NN    16
#define THREADS 256
#define ROWB    80
#define PLANE   (128 * ROWB)     // 10240 B
#define STAGE   (4 * PLANE)      // 40960 B
#define DSTR    129

#define OFF_SQI   (2 * STAGE)              // 81920
#define OFF_SQJ   (OFF_SQI + TM * 4)
#define SMEM_TOT  (OFF_SQJ + TN * 4)       // 82944

typedef unsigned long long u64;

__device__ float g_sq[1 << 17];
__device__ __nv_bfloat16 g_hi[1 << 24];
__device__ __nv_bfloat16 g_lo[1 << 24];
__device__ u64 g_pk[1 << 23];              // packed partials (dist_bits<<32 | idx)

__device__ __forceinline__ uint32_t smem_u32(const void* p) {
    uint32_t a;
    asm("{ .reg .u64 t; cvta.to.shared.u64 t, %1; cvt.u32.u64 %0, t; }" : "=r"(a) : "l"(p));
    return a;
}
__device__ __forceinline__ void ldm_x4(uint32_t* r, uint32_t addr) {
    asm volatile("ldmatrix.sync.aligned.m8n8.x4.shared.b16 {%0,%1,%2,%3}, [%4];"
                 : "=r"(r[0]), "=r"(r[1]), "=r"(r[2]), "=r"(r[3]) : "r"(addr));
}
__device__ __forceinline__ void mma_bf16(float* c, const uint32_t* a, uint32_t b0, uint32_t b1) {
    asm volatile(
        "mma.sync.aligned.m16n8k16.row.col.f32.bf16.bf16.f32 "
        "{%0,%1,%2,%3},{%4,%5,%6,%7},{%8,%9},{%0,%1,%2,%3};"
        : "+f"(c[0]), "+f"(c[1]), "+f"(c[2]), "+f"(c[3])
        : "r"(a[0]), "r"(a[1]), "r"(a[2]), "r"(a[3]), "r"(b0), "r"(b1));
}
__device__ __forceinline__ void cp16(uint32_t dst, const void* src) {
    asm volatile("cp.async.cg.shared.global [%0], [%1], 16;" :: "r"(dst), "l"(src));
}
__device__ __forceinline__ uint32_t pk(float a, float b) {
    __nv_bfloat16 x = __float2bfloat16(a), y = __float2bfloat16(b);
    return (uint32_t)__bfloat16_as_ushort(x) | ((uint32_t)__bfloat16_as_ushort(y) << 16);
}
__device__ __forceinline__ u64 mk_key(float d, int idx) {
    d = fmaxf(d, 0.f);                      // uint-order needs non-negative
    return ((u64)__float_as_uint(d) << 32) | (uint32_t)idx;
}
// 16-deep sorted insert (ascending; equal dist -> smaller idx kept first)
__device__ __forceinline__ void ins_key(u64 key, u64* hp, u64& w) {
#pragma unroll
    for (int t = K_NN - 1; t >= 1; --t) {
        if (hp[t - 1] > key) hp[t] = hp[t - 1];
        else if (hp[t] > key) hp[t] = key;
    }
    if (hp[0] > key) hp[0] = key;
    w = hp[K_NN - 1];
}

// ---------------------------------------------------------------------------
__global__ void prep_kernel(const float* __restrict__ h, int n_rows) {
    int row  = blockIdx.x * 8 + (threadIdx.x >> 5);
    int lane = threadIdx.x & 31;
    if (row >= n_rows) return;
    const float4* h4 = (const float4*)(h + (size_t)row * D_DIM);
    float4 v0 = h4[2 * lane], v1 = h4[2 * lane + 1];
    float s = v0.x * v0.x + v0.y * v0.y + v0.z * v0.z + v0.w * v0.w
            + v1.x * v1.x + v1.y * v1.y + v1.z * v1.z + v1.w * v1.w;
#pragma unroll
    for (int o = 16; o > 0; o >>= 1)
        s += __shfl_xor_sync(0xffffffffu, s, o);
    if (lane == 0) g_sq[row] = s;

    float f[8] = {v0.x, v0.y, v0.z, v0.w, v1.x, v1.y, v1.z, v1.w};
    float hi[8], lo[8];
#pragma unroll
    for (int q = 0; q < 8; ++q) {
        hi[q] = __bfloat162float(__float2bfloat16(f[q]));
        lo[q] = f[q] - hi[q];
    }
    size_t off = (size_t)row * D_DIM + lane * 8;
    *(uint4*)(g_hi + off) = make_uint4(pk(hi[0], hi[1]), pk(hi[2], hi[3]),
                                       pk(hi[4], hi[5]), pk(hi[6], hi[7]));
    *(uint4*)(g_lo + off) = make_uint4(pk(lo[0], lo[1]), pk(lo[2], lo[3]),
                                       pk(lo[4], lo[5]), pk(lo[6], lo[7]));
}

// ---------------------------------------------------------------------------
// One CTA per UPPER-TRIANGULAR (i,j)-tile. 256 threads, warp grid 2(m)x4(n).
// Row scan on threads 0-127, column scan on threads 128-255, concurrent.
// ---------------------------------------------------------------------------
__global__ void __launch_bounds__(THREADS, 2)
knn_part(int L, int NTJ) {
    extern __shared__ char sm[];
    const uint32_t sb = smem_u32(sm);
    float* dbuf = (float*)sm;
    float* sqi  = (float*)(sm + OFF_SQI);
    float* sqj  = (float*)(sm + OFF_SQJ);

    int u = blockIdx.x, ti = 0;
    while (u >= NTJ - ti) { u -= NTJ - ti; ++ti; }
    const int tj  = ti + u;
    const int i0  = ti * TM;
    const int jt  = tj * TN;
    const int b   = blockIdx.z;
    const int tid = threadIdx.x;
    const int lane = tid & 31;
    const int wid  = tid >> 5;
    const int wm   = wid >> 2;
    const int wn   = wid & 3;
    const size_t rowbase = (size_t)b * L;

    if (tid < TM) sqi[tid] = g_sq[rowbase + i0 + tid];
    if (tid < TN) sqj[tid] = g_sq[rowbase + jt + tid];

    const int lanem = lane & 15;
    const int laneh = (lane >> 4) * 16;
    uint32_t a_rel[4], b_rel[2];
#pragma unroll
    for (int mi = 0; mi < 4; ++mi)
        a_rel[mi] = sb + (uint32_t)(wm * 64 + 16 * mi + lanem) * ROWB + laneh;
#pragma unroll
    for (int g = 0; g < 2; ++g)
        b_rel[g] = sb + 2 * PLANE + (uint32_t)(wn * 32 + 16 * g + lanem) * ROWB + laneh;

    const int s_plane = tid >> 6;
    const int s_r     = (tid >> 2) & 15;
    const int s_seg   = tid & 3;

    float acc[4][4][4];
#pragma unroll
    for (int mi = 0; mi < 4; ++mi)
#pragma unroll
        for (int ni = 0; ni < 4; ++ni)
#pragma unroll
            for (int q = 0; q < 4; ++q) acc[mi][ni][q] = 0.f;

#pragma unroll
    for (int p = 0; p < 8; ++p) {
        int r = s_r + 16 * p;
        const __nv_bfloat16* gp = (s_plane & 1) ? g_lo : g_hi;
        size_t row = rowbase + ((s_plane < 2) ? (i0 + r) : (jt + r));
        cp16(sb + (uint32_t)s_plane * PLANE + (uint32_t)r * ROWB + (uint32_t)s_seg * 16,
             gp + row * D_DIM + s_seg * 8);
    }
    asm volatile("cp.async.commit_group;" ::: "memory");

#pragma unroll 1
    for (int c = 0; c < NCH; ++c) {
        const uint32_t bufo = (uint32_t)(c & 1) * STAGE;
        if (c + 1 < NCH) {
            int kb = (c + 1) * KC;
            const uint32_t nb = (uint32_t)((c + 1) & 1) * STAGE;
#pragma unroll
            for (int p = 0; p < 8; ++p) {
                int r = s_r + 16 * p;
                const __nv_bfloat16* gp = (s_plane & 1) ? g_lo : g_hi;
                size_t row = rowbase + ((s_plane < 2) ? (i0 + r) : (jt + r));
                cp16(nb + sb + (uint32_t)s_plane * PLANE + (uint32_t)r * ROWB + (uint32_t)s_seg * 16,
                     gp + row * D_DIM + kb + s_seg * 8);
            }
            asm volatile("cp.async.commit_group;" ::: "memory");
            asm volatile("cp.async.wait_group 1;" ::: "memory");
        } else {
            asm volatile("cp.async.wait_group 0;" ::: "memory");
        }
        __syncthreads();

#pragma unroll
        for (int ks = 0; ks < 2; ++ks) {
            const uint32_t ko = bufo + (uint32_t)ks * 32;
            uint32_t ahi[4][4], alo[4][4], bb[2][4];
#pragma unroll
            for (int mi = 0; mi < 4; ++mi) {
                ldm_x4(ahi[mi], a_rel[mi] + ko);
                ldm_x4(alo[mi], a_rel[mi] + ko + PLANE);
            }
#pragma unroll
            for (int g = 0; g < 2; ++g) ldm_x4(bb[g], b_rel[g] + ko);         // B hi
#pragma unroll
            for (int mi = 0; mi < 4; ++mi)
#pragma unroll
                for (int ni = 0; ni < 4; ++ni)
                    mma_bf16(acc[mi][ni], ahi[mi], bb[ni >> 1][ni & 1], bb[ni >> 1][(ni & 1) + 2]);
#pragma unroll
            for (int mi = 0; mi < 4; ++mi)
#pragma unroll
                for (int ni = 0; ni < 4; ++ni)
                    mma_bf16(acc[mi][ni], alo[mi], bb[ni >> 1][ni & 1], bb[ni >> 1][(ni & 1) + 2]);
#pragma unroll
            for (int g = 0; g < 2; ++g) ldm_x4(bb[g], b_rel[g] + ko + PLANE); // B lo
#pragma unroll
            for (int mi = 0; mi < 4; ++mi)
#pragma unroll
                for (int ni = 0; ni < 4; ++ni)
                    mma_bf16(acc[mi][ni], ahi[mi], bb[ni >> 1][ni & 1], bb[ni >> 1][(ni & 1) + 2]);
        }
        __syncthreads();
    }

    // epilogue: distances into dbuf
#pragma unroll
    for (int mi = 0; mi < 4; ++mi) {
        int   r0  = wm * 64 + mi * 16 + (lane >> 2);
        float si0 = sqi[r0], si1 = sqi[r0 + 8];
#pragma unroll
        for (int ni = 0; ni < 4; ++ni) {
            int cl = wn * 32 + ni * 8 + 2 * (lane & 3);
            float sj0 = sqj[cl], sj1 = sqj[cl + 1];
            dbuf[r0 * DSTR + cl]           = si0 + sj0 - 2.f * acc[mi][ni][0];
            dbuf[r0 * DSTR + cl + 1]       = si0 + sj1 - 2.f * acc[mi][ni][1];
            dbuf[(r0 + 8) * DSTR + cl]     = si1 + sj0 - 2.f * acc[mi][ni][2];
            dbuf[(r0 + 8) * DSTR + cl + 1] = si1 + sj1 - 2.f * acc[mi][ni][3];
        }
    }
    __syncthreads();

    // concurrent scans with full-precision u64 keys
    if (tid < TM) {
        u64 hp[K_NN];
#pragma unroll
        for (int t = 0; t < K_NN; ++t) hp[t] = ~0ull;
        u64 w = ~0ull;
        const float* drow = &dbuf[tid * DSTR];
#pragma unroll 1
        for (int j = 0; j < TN; ++j) {
            u64 key = mk_key(drow[j], jt + j);
            if (key < w) ins_key(key, hp, w);
        }
        size_t base = ((size_t)(rowbase + i0 + tid) * NTJ + tj) * K_NN;
#pragma unroll
        for (int t = 0; t < K_NN; ++t) g_pk[base + t] = hp[t];
    } else if (ti != tj) {
        const int col = tid - TM;
        u64 hp[K_NN];
#pragma unroll
        for (int t = 0; t < K_NN; ++t) hp[t] = ~0ull;
        u64 w = ~0ull;
#pragma unroll 1
        for (int r = 0; r < TM; ++r) {
            u64 key = mk_key(dbuf[r * DSTR + col], i0 + r);
            if (key < w) ins_key(key, hp, w);
        }
        size_t base = ((size_t)(rowbase + jt + col) * NTJ + ti) * K_NN;
#pragma unroll
        for (int t = 0; t < K_NN; ++t) g_pk[base + t] = hp[t];
    }
}

// ---------------------------------------------------------------------------
__global__ void merge_kernel(float* __restrict__ out_d, float* __restrict__ out_s,
                             float* __restrict__ out_t,
                             int L, int NTJ, int write_idx, int n_rows) {
    int row = blockIdx.x * blockDim.x + threadIdx.x;
    if (row >= n_rows) return;
    u64 hp[K_NN];
#pragma unroll
    for (int t = 0; t < K_NN; ++t) hp[t] = ~0ull;
    u64 w = ~0ull;
    size_t base = (size_t)row * NTJ * K_NN;
#pragma unroll 1
    for (int tj = 0; tj < NTJ; ++tj) {
#pragma unroll 1
        for (int t = 0; t < K_NN; ++t) {
            u64 k = g_pk[base + tj * K_NN + t];
            if (k >= w) break;              // list sorted ascending
            ins_key(k, hp, w);
        }
    }
    size_t rowbase = (size_t)(row / L) * L;
    float  srcv = (float)row;
    float* dd = out_d + (size_t)row * K_NN;
#pragma unroll
    for (int t = 0; t < K_NN; ++t) dd[t] = __uint_as_float((uint32_t)(hp[t] >> 32));
    if (write_idx) {
        float* ds = out_s + (size_t)row * K_NN;
        float* dt = out_t + (size_t)row * K_NN;
#pragma unroll
        for (int t = 0; t < K_NN; ++t) {
            ds[t] = srcv;
            dt[t] = (float)(rowbase + (uint32_t)(hp[t] & 0xFFFFFFFFu));
        }
    }
}

// ---------------------------------------------------------------------------
extern "C" void kernel_launch(void* const* d_in, const int* in_sizes, int n_in,
                              void* d_out, int out_size) {
    const float* h = (const float*)d_in[0];
    int B = in_sizes[1];
    int n_rows = in_sizes[0] / D_DIM;
    int L = n_rows / B;
    int NTJ = L / TN;

    float* out_d = (float*)d_out;
    size_t Nd = (size_t)n_rows * K_NN;
    int three = (size_t)out_size >= 3 * Nd;
    float* out_s = three ? out_d + Nd : out_d;
    float* out_t = three ? out_d + 2 * Nd : out_d;

    cudaFuncSetAttribute(knn_part, cudaFuncAttributeMaxDynamicSharedMemorySize, SMEM_TOT);

    prep_kernel<<<(n_rows + 7) / 8, 256>>>(h, n_rows);
    dim3 grid(NTJ * (NTJ + 1) / 2, 1, B);
    knn_part<<<grid, THREADS, SMEM_TOT>>>(L, NTJ);
    merge_kernel<<<(n_rows + 255) / 256, 256>>>(out_d, out_s, out_t, L, NTJ, three, n_rows);
}

// round 14
// speedup vs baseline: 1.3191x; 1.3191x over previous
#include <cuda_runtime.h>
#include <cuda_bf16.h>
#include <stdint.h>

#define D_DIM   256
#define TM      128
#define TN      128
#define KC      32
#define NCH     (D_DIM / KC)
#define K_NN    16
#define THREADS 256
#define ROWB    80
#define PLANE   (128 * ROWB)     // 10240 B
#define STAGE   (4 * PLANE)      // 40960 B
#define DSTR    129

#define OFF_SQI   (2 * STAGE)              // 81920
#define OFF_SQJ   (OFF_SQI + TM * 4)
#define SMEM_TOT  (OFF_SQJ + TN * 4)       // 82944

__device__ float g_sq[1 << 17];
__device__ __nv_bfloat16 g_hi[1 << 24];
__device__ __nv_bfloat16 g_lo[1 << 24];
__device__ float2 g_pc[1 << 23];           // partials TRANSPOSED: [tile][k][row]

__device__ __forceinline__ uint32_t smem_u32(const void* p) {
    uint32_t a;
    asm("{ .reg .u64 t; cvta.to.shared.u64 t, %1; cvt.u32.u64 %0, t; }" : "=r"(a) : "l"(p));
    return a;
}
__device__ __forceinline__ void ldm_x4(uint32_t* r, uint32_t addr) {
    asm volatile("ldmatrix.sync.aligned.m8n8.x4.shared.b16 {%0,%1,%2,%3}, [%4];"
                 : "=r"(r[0]), "=r"(r[1]), "=r"(r[2]), "=r"(r[3]) : "r"(addr));
}
__device__ __forceinline__ void mma_bf16(float* c, const uint32_t* a, uint32_t b0, uint32_t b1) {
    asm volatile(
        "mma.sync.aligned.m16n8k16.row.col.f32.bf16.bf16.f32 "
        "{%0,%1,%2,%3},{%4,%5,%6,%7},{%8,%9},{%0,%1,%2,%3};"
        : "+f"(c[0]), "+f"(c[1]), "+f"(c[2]), "+f"(c[3])
        : "r"(a[0]), "r"(a[1]), "r"(a[2]), "r"(a[3]), "r"(b0), "r"(b1));
}
__device__ __forceinline__ void cp16(uint32_t dst, const void* src) {
    asm volatile("cp.async.cg.shared.global [%0], [%1], 16;" :: "r"(dst), "l"(src));
}
__device__ __forceinline__ uint32_t pk(float a, float b) {
    __nv_bfloat16 x = __float2bfloat16(a), y = __float2bfloat16(b);
    return (uint32_t)__bfloat16_as_ushort(x) | ((uint32_t)__bfloat16_as_ushort(y) << 16);
}

// ---------------------------------------------------------------------------
__global__ void prep_kernel(const float* __restrict__ h, int n_rows) {
    int row  = blockIdx.x * 8 + (threadIdx.x >> 5);
    int lane = threadIdx.x & 31;
    if (row >= n_rows) return;
    const float4* h4 = (const float4*)(h + (size_t)row * D_DIM);
    float4 v0 = h4[2 * lane], v1 = h4[2 * lane + 1];
    float s = v0.x * v0.x + v0.y * v0.y + v0.z * v0.z + v0.w * v0.w
            + v1.x * v1.x + v1.y * v1.y + v1.z * v1.z + v1.w * v1.w;
#pragma unroll
    for (int o = 16; o > 0; o >>= 1)
        s += __shfl_xor_sync(0xffffffffu, s, o);
    if (lane == 0) g_sq[row] = s;

    float f[8] = {v0.x, v0.y, v0.z, v0.w, v1.x, v1.y, v1.z, v1.w};
    float hi[8], lo[8];
#pragma unroll
    for (int q = 0; q < 8; ++q) {
        hi[q] = __bfloat162float(__float2bfloat16(f[q]));
        lo[q] = f[q] - hi[q];
    }
    size_t off = (size_t)row * D_DIM + lane * 8;
    *(uint4*)(g_hi + off) = make_uint4(pk(hi[0], hi[1]), pk(hi[2], hi[3]),
                                       pk(hi[4], hi[5]), pk(hi[6], hi[7]));
    *(uint4*)(g_lo + off) = make_uint4(pk(lo[0], lo[1]), pk(lo[2], lo[3]),
                                       pk(lo[4], lo[5]), pk(lo[6], lo[7]));
}

// ---------------------------------------------------------------------------
__device__ __forceinline__ void scan_insert(float d, int jg, float* hp, int* hx, float& w) {
    if (d < w) {
#pragma unroll
        for (int t = K_NN - 1; t >= 1; --t) {
            if (hp[t - 1] > d)  { hp[t] = hp[t - 1]; hx[t] = hx[t - 1]; }
            else if (hp[t] > d) { hp[t] = d;         hx[t] = jg; }
        }
        if (hp[0] > d)          { hp[0] = d;         hx[0] = jg; }
        w = hp[K_NN - 1];
    }
}

// ---------------------------------------------------------------------------
// One CTA per UPPER-TRIANGULAR (i,j)-tile. Row scan on threads 0-127, column
// scan on threads 128-255, concurrent. Warp grid 2(m) x 4(n).
// Partials stored transposed [tile][k][row] for coalesced writes + merge reads.
// ---------------------------------------------------------------------------
__global__ void __launch_bounds__(THREADS, 2)
knn_part(int L, int NTJ, int n_rows) {
    extern __shared__ char sm[];
    const uint32_t sb = smem_u32(sm);
    float* dbuf = (float*)sm;
    float* sqi  = (float*)(sm + OFF_SQI);
    float* sqj  = (float*)(sm + OFF_SQJ);

    int u = blockIdx.x, ti = 0;
    while (u >= NTJ - ti) { u -= NTJ - ti; ++ti; }
    const int tj  = ti + u;
    const int i0  = ti * TM;
    const int jt  = tj * TN;
    const int b   = blockIdx.z;
    const int tid = threadIdx.x;
    const int lane = tid & 31;
    const int wid  = tid >> 5;
    const int wm   = wid >> 2;
    const int wn   = wid & 3;
    const size_t rowbase = (size_t)b * L;

    if (tid < TM) sqi[tid] = g_sq[rowbase + i0 + tid];
    if (tid < TN) sqj[tid] = g_sq[rowbase + jt + tid];

    const int lanem = lane & 15;
    const int laneh = (lane >> 4) * 16;
    uint32_t a_rel[4], b_rel[2];
#pragma unroll
    for (int mi = 0; mi < 4; ++mi)
        a_rel[mi] = sb + (uint32_t)(wm * 64 + 16 * mi + lanem) * ROWB + laneh;
#pragma unroll
    for (int g = 0; g < 2; ++g)
        b_rel[g] = sb + 2 * PLANE + (uint32_t)(wn * 32 + 16 * g + lanem) * ROWB + laneh;

    const int s_plane = tid >> 6;
    const int s_r     = (tid >> 2) & 15;
    const int s_seg   = tid & 3;

    float acc[4][4][4];
#pragma unroll
    for (int mi = 0; mi < 4; ++mi)
#pragma unroll
        for (int ni = 0; ni < 4; ++ni)
#pragma unroll
            for (int q = 0; q < 4; ++q) acc[mi][ni][q] = 0.f;

#pragma unroll
    for (int p = 0; p < 8; ++p) {
        int r = s_r + 16 * p;
        const __nv_bfloat16* gp = (s_plane & 1) ? g_lo : g_hi;
        size_t row = rowbase + ((s_plane < 2) ? (i0 + r) : (jt + r));
        cp16(sb + (uint32_t)s_plane * PLANE + (uint32_t)r * ROWB + (uint32_t)s_seg * 16,
             gp + row * D_DIM + s_seg * 8);
    }
    asm volatile("cp.async.commit_group;" ::: "memory");

#pragma unroll 1
    for (int c = 0; c < NCH; ++c) {
        const uint32_t bufo = (uint32_t)(c & 1) * STAGE;
        if (c + 1 < NCH) {
            int kb = (c + 1) * KC;
            const uint32_t nb = (uint32_t)((c + 1) & 1) * STAGE;
#pragma unroll
            for (int p = 0; p < 8; ++p) {
                int r = s_r + 16 * p;
                const __nv_bfloat16* gp = (s_plane & 1) ? g_lo : g_hi;
                size_t row = rowbase + ((s_plane < 2) ? (i0 + r) : (jt + r));
                cp16(nb + sb + (uint32_t)s_plane * PLANE + (uint32_t)r * ROWB + (uint32_t)s_seg * 16,
                     gp + row * D_DIM + kb + s_seg * 8);
            }
            asm volatile("cp.async.commit_group;" ::: "memory");
            asm volatile("cp.async.wait_group 1;" ::: "memory");
        } else {
            asm volatile("cp.async.wait_group 0;" ::: "memory");
        }
        __syncthreads();

#pragma unroll
        for (int ks = 0; ks < 2; ++ks) {
            const uint32_t ko = bufo + (uint32_t)ks * 32;
            uint32_t ahi[4][4], alo[4][4], bb[2][4];
#pragma unroll
            for (int mi = 0; mi < 4; ++mi) {
                ldm_x4(ahi[mi], a_rel[mi] + ko);
                ldm_x4(alo[mi], a_rel[mi] + ko + PLANE);
            }
#pragma unroll
            for (int g = 0; g < 2; ++g) ldm_x4(bb[g], b_rel[g] + ko);         // B hi
#pragma unroll
            for (int mi = 0; mi < 4; ++mi)
#pragma unroll
                for (int ni = 0; ni < 4; ++ni)
                    mma_bf16(acc[mi][ni], ahi[mi], bb[ni >> 1][ni & 1], bb[ni >> 1][(ni & 1) + 2]);
#pragma unroll
            for (int mi = 0; mi < 4; ++mi)
#pragma unroll
                for (int ni = 0; ni < 4; ++ni)
                    mma_bf16(acc[mi][ni], alo[mi], bb[ni >> 1][ni & 1], bb[ni >> 1][(ni & 1) + 2]);
#pragma unroll
            for (int g = 0; g < 2; ++g) ldm_x4(bb[g], b_rel[g] + ko + PLANE); // B lo
#pragma unroll
            for (int mi = 0; mi < 4; ++mi)
#pragma unroll
                for (int ni = 0; ni < 4; ++ni)
                    mma_bf16(acc[mi][ni], ahi[mi], bb[ni >> 1][ni & 1], bb[ni >> 1][(ni & 1) + 2]);
        }
        __syncthreads();
    }

    // epilogue: distances into dbuf
#pragma unroll
    for (int mi = 0; mi < 4; ++mi) {
        int   r0  = wm * 64 + mi * 16 + (lane >> 2);
        float si0 = sqi[r0], si1 = sqi[r0 + 8];
#pragma unroll
        for (int ni = 0; ni < 4; ++ni) {
            int cl = wn * 32 + ni * 8 + 2 * (lane & 3);
            float sj0 = sqj[cl], sj1 = sqj[cl + 1];
            dbuf[r0 * DSTR + cl]           = si0 + sj0 - 2.f * acc[mi][ni][0];
            dbuf[r0 * DSTR + cl + 1]       = si0 + sj1 - 2.f * acc[mi][ni][1];
            dbuf[(r0 + 8) * DSTR + cl]     = si1 + sj0 - 2.f * acc[mi][ni][2];
            dbuf[(r0 + 8) * DSTR + cl + 1] = si1 + sj1 - 2.f * acc[mi][ni][3];
        }
    }
    __syncthreads();

    // concurrent scans; partial lists stored transposed: [tile][k][row]
    if (tid < TM) {
        float hp[K_NN];
        int   hx[K_NN];
#pragma unroll
        for (int t = 0; t < K_NN; ++t) { hp[t] = 3.4e38f; hx[t] = 0; }
        const float* drow = &dbuf[tid * DSTR];
        float w = 3.4e38f;
#pragma unroll 1
        for (int j = 0; j < TN; ++j)
            scan_insert(drow[j], jt + j, hp, hx, w);
        size_t row = rowbase + i0 + tid;
#pragma unroll
        for (int t = 0; t < K_NN; ++t)
            g_pc[((size_t)tj * K_NN + t) * n_rows + row] = make_float2(hp[t], (float)hx[t]);
    } else if (ti != tj) {
        const int col = tid - TM;
        float hp[K_NN];
        int   hx[K_NN];
#pragma unroll
        for (int t = 0; t < K_NN; ++t) { hp[t] = 3.4e38f; hx[t] = 0; }
        float w = 3.4e38f;
#pragma unroll 1
        for (int r = 0; r < TM; ++r)
            scan_insert(dbuf[r * DSTR + col], i0 + r, hp, hx, w);
        size_t row = rowbase + jt + col;
#pragma unroll
        for (int t = 0; t < K_NN; ++t)
            g_pc[((size_t)ti * K_NN + t) * n_rows + row] = make_float2(hp[t], (float)hx[t]);
    }
}

// ---------------------------------------------------------------------------
__global__ void merge_kernel(float* __restrict__ out_d, float* __restrict__ out_s,
                             float* __restrict__ out_t,
                             int L, int NTJ, int write_idx, int n_rows) {
    int row = blockIdx.x * blockDim.x + threadIdx.x;
    if (row >= n_rows) return;
    float hp[K_NN];
    int   hx[K_NN];
#pragma unroll
    for (int t = 0; t < K_NN; ++t) { hp[t] = 3.4e38f; hx[t] = 0; }
    float w = 3.4e38f;
#pragma unroll 1
    for (int tj = 0; tj < NTJ; ++tj) {
#pragma unroll 1
        for (int t = 0; t < K_NN; ++t) {
            float2 c = g_pc[((size_t)tj * K_NN + t) * n_rows + row];
            float d = c.x;
            if (d >= w) break;              // list sorted ascending
            int jg = (int)c.y;
#pragma unroll
            for (int u = K_NN - 1; u >= 1; --u) {
                if (hp[u - 1] > d)  { hp[u] = hp[u - 1]; hx[u] = hx[u - 1]; }
                else if (hp[u] > d) { hp[u] = d;         hx[u] = jg; }
            }
            if (hp[0] > d)          { hp[0] = d;         hx[0] = jg; }
            w = hp[K_NN - 1];
        }
    }
    size_t rowbase = (size_t)(row / L) * L;
    float  srcv = (float)row;
    float* dd = out_d + (size_t)row * K_NN;
#pragma unroll
    for (int t = 0; t < K_NN; ++t) dd[t] = hp[t];
    if (write_idx) {
        float* ds = out_s + (size_t)row * K_NN;
        float* dt = out_t + (size_t)row * K_NN;
#pragma unroll
        for (int t = 0; t < K_NN; ++t) {
            ds[t] = srcv;
            dt[t] = (float)(rowbase + hx[t]);
        }
    }
}

// ---------------------------------------------------------------------------
extern "C" void kernel_launch(void* const* d_in, const int* in_sizes, int n_in,
                              void* d_out, int out_size) {
    const float* h = (const float*)d_in[0];
    int B = in_sizes[1];
    int n_rows = in_sizes[0] / D_DIM;
    int L = n_rows / B;
    int NTJ = L / TN;

    float* out_d = (float*)d_out;
    size_t Nd = (size_t)n_rows * K_NN;
    int three = (size_t)out_size >= 3 * Nd;
    float* out_s = three ? out_d + Nd : out_d;
    float* out_t = three ? out_d + 2 * Nd : out_d;

    cudaFuncSetAttribute(knn_part, cudaFuncAttributeMaxDynamicSharedMemorySize, SMEM_TOT);

    prep_kernel<<<(n_rows + 7) / 8, 256>>>(h, n_rows);
    dim3 grid(NTJ * (NTJ + 1) / 2, 1, B);
    knn_part<<<grid, THREADS, SMEM_TOT>>>(L, NTJ, n_rows);
    merge_kernel<<<(n_rows + 255) / 256, 256>>>(out_d, out_s, out_t, L, NTJ, three, n_rows);
}

// round 15
// speedup vs baseline: 1.3990x; 1.0606x over previous
#include <cuda_runtime.h>
#include <cuda_bf16.h>
#include <stdint.h>

#define D_DIM   256
#define TM      128
#define TN      128
#define KC      32
#define NCH     (D_DIM / KC)
#define K_NN    16
#define THREADS 256
#define ROWB    80
#define PLANE   (128 * ROWB)     // 10240 B
#define STAGE   (4 * PLANE)      // 40960 B
#define DSTR    132              // 132*4=528B rows: 16B-aligned, conflict-free scans

#define OFF_SQI   (2 * STAGE)              // 81920
#define OFF_SQJ   (OFF_SQI + TM * 4)
#define SMEM_TOT  (OFF_SQJ + TN * 4)       // 82944

__device__ float g_sq[1 << 17];
__device__ __nv_bfloat16 g_hi[1 << 24];
__device__ __nv_bfloat16 g_lo[1 << 24];
__device__ float2 g_pc[1 << 23];           // partials transposed: [tile][k][row]

__device__ __forceinline__ uint32_t smem_u32(const void* p) {
    uint32_t a;
    asm("{ .reg .u64 t; cvta.to.shared.u64 t, %1; cvt.u32.u64 %0, t; }" : "=r"(a) : "l"(p));
    return a;
}
__device__ __forceinline__ void ldm_x4(uint32_t* r, uint32_t addr) {
    asm volatile("ldmatrix.sync.aligned.m8n8.x4.shared.b16 {%0,%1,%2,%3}, [%4];"
                 : "=r"(r[0]), "=r"(r[1]), "=r"(r[2]), "=r"(r[3]) : "r"(addr));
}
__device__ __forceinline__ void mma_bf16(float* c, const uint32_t* a, uint32_t b0, uint32_t b1) {
    asm volatile(
        "mma.sync.aligned.m16n8k16.row.col.f32.bf16.bf16.f32 "
        "{%0,%1,%2,%3},{%4,%5,%6,%7},{%8,%9},{%0,%1,%2,%3};"
        : "+f"(c[0]), "+f"(c[1]), "+f"(c[2]), "+f"(c[3])
        : "r"(a[0]), "r"(a[1]), "r"(a[2]), "r"(a[3]), "r"(b0), "r"(b1));
}
__device__ __forceinline__ void cp16(uint32_t dst, const void* src) {
    asm volatile("cp.async.cg.shared.global [%0], [%1], 16;" :: "r"(dst), "l"(src));
}
__device__ __forceinline__ uint32_t pk(float a, float b) {
    __nv_bfloat16 x = __float2bfloat16(a), y = __float2bfloat16(b);
    return (uint32_t)__bfloat16_as_ushort(x) | ((uint32_t)__bfloat16_as_ushort(y) << 16);
}

// ---------------------------------------------------------------------------
__global__ void prep_kernel(const float* __restrict__ h, int n_rows) {
    int row  = blockIdx.x * 8 + (threadIdx.x >> 5);
    int lane = threadIdx.x & 31;
    if (row >= n_rows) return;
    const float4* h4 = (const float4*)(h + (size_t)row * D_DIM);
    float4 v0 = h4[2 * lane], v1 = h4[2 * lane + 1];
    float s = v0.x * v0.x + v0.y * v0.y + v0.z * v0.z + v0.w * v0.w
            + v1.x * v1.x + v1.y * v1.y + v1.z * v1.z + v1.w * v1.w;
#pragma unroll
    for (int o = 16; o > 0; o >>= 1)
        s += __shfl_xor_sync(0xffffffffu, s, o);
    if (lane == 0) g_sq[row] = s;

    float f[8] = {v0.x, v0.y, v0.z, v0.w, v1.x, v1.y, v1.z, v1.w};
    float hi[8], lo[8];
#pragma unroll
    for (int q = 0; q < 8; ++q) {
        hi[q] = __bfloat162float(__float2bfloat16(f[q]));
        lo[q] = f[q] - hi[q];
    }
    size_t off = (size_t)row * D_DIM + lane * 8;
    *(uint4*)(g_hi + off) = make_uint4(pk(hi[0], hi[1]), pk(hi[2], hi[3]),
                                       pk(hi[4], hi[5]), pk(hi[6], hi[7]));
    *(uint4*)(g_lo + off) = make_uint4(pk(lo[0], lo[1]), pk(lo[2], lo[3]),
                                       pk(lo[4], lo[5]), pk(lo[6], lo[7]));
}

// ---------------------------------------------------------------------------
__device__ __forceinline__ void ins1(float d, int jg, float* hp, int* hx, float& w) {
    if (d < w) {
#pragma unroll
        for (int t = K_NN - 1; t >= 1; --t) {
            if (hp[t - 1] > d)  { hp[t] = hp[t - 1]; hx[t] = hx[t - 1]; }
            else if (hp[t] > d) { hp[t] = d;         hx[t] = jg; }
        }
        if (hp[0] > d)          { hp[0] = d;         hx[0] = jg; }
        w = hp[K_NN - 1];
    }
}

// ---------------------------------------------------------------------------
// One CTA per UPPER-TRIANGULAR (i,j)-tile. Concurrent row/col scans with
// 4-wide batched-min filtering. Warp grid 2(m) x 4(n).
// ---------------------------------------------------------------------------
__global__ void __launch_bounds__(THREADS, 2)
knn_part(int L, int NTJ, int n_rows) {
    extern __shared__ char sm[];
    const uint32_t sb = smem_u32(sm);
    float* dbuf = (float*)sm;
    float* sqi  = (float*)(sm + OFF_SQI);
    float* sqj  = (float*)(sm + OFF_SQJ);

    int u = blockIdx.x, ti = 0;
    while (u >= NTJ - ti) { u -= NTJ - ti; ++ti; }
    const int tj  = ti + u;
    const int i0  = ti * TM;
    const int jt  = tj * TN;
    const int b   = blockIdx.z;
    const int tid = threadIdx.x;
    const int lane = tid & 31;
    const int wid  = tid >> 5;
    const int wm   = wid >> 2;
    const int wn   = wid & 3;
    const size_t rowbase = (size_t)b * L;

    if (tid < TM) sqi[tid] = g_sq[rowbase + i0 + tid];
    if (tid < TN) sqj[tid] = g_sq[rowbase + jt + tid];

    const int lanem = lane & 15;
    const int laneh = (lane >> 4) * 16;
    uint32_t a_rel[4], b_rel[2];
#pragma unroll
    for (int mi = 0; mi < 4; ++mi)
        a_rel[mi] = sb + (uint32_t)(wm * 64 + 16 * mi + lanem) * ROWB + laneh;
#pragma unroll
    for (int g = 0; g < 2; ++g)
        b_rel[g] = sb + 2 * PLANE + (uint32_t)(wn * 32 + 16 * g + lanem) * ROWB + laneh;

    const int s_plane = tid >> 6;
    const int s_r     = (tid >> 2) & 15;
    const int s_seg   = tid & 3;

    float acc[4][4][4];
#pragma unroll
    for (int mi = 0; mi < 4; ++mi)
#pragma unroll
        for (int ni = 0; ni < 4; ++ni)
#pragma unroll
            for (int q = 0; q < 4; ++q) acc[mi][ni][q] = 0.f;

#pragma unroll
    for (int p = 0; p < 8; ++p) {
        int r = s_r + 16 * p;
        const __nv_bfloat16* gp = (s_plane & 1) ? g_lo : g_hi;
        size_t row = rowbase + ((s_plane < 2) ? (i0 + r) : (jt + r));
        cp16(sb + (uint32_t)s_plane * PLANE + (uint32_t)r * ROWB + (uint32_t)s_seg * 16,
             gp + row * D_DIM + s_seg * 8);
    }
    asm volatile("cp.async.commit_group;" ::: "memory");

#pragma unroll 1
    for (int c = 0; c < NCH; ++c) {
        const uint32_t bufo = (uint32_t)(c & 1) * STAGE;
        if (c + 1 < NCH) {
            int kb = (c + 1) * KC;
            const uint32_t nb = (uint32_t)((c + 1) & 1) * STAGE;
#pragma unroll
            for (int p = 0; p < 8; ++p) {
                int r = s_r + 16 * p;
                const __nv_bfloat16* gp = (s_plane & 1) ? g_lo : g_hi;
                size_t row = rowbase + ((s_plane < 2) ? (i0 + r) : (jt + r));
                cp16(nb + sb + (uint32_t)s_plane * PLANE + (uint32_t)r * ROWB + (uint32_t)s_seg * 16,
                     gp + row * D_DIM + kb + s_seg * 8);
            }
            asm volatile("cp.async.commit_group;" ::: "memory");
            asm volatile("cp.async.wait_group 1;" ::: "memory");
        } else {
            asm volatile("cp.async.wait_group 0;" ::: "memory");
        }
        __syncthreads();

#pragma unroll
        for (int ks = 0; ks < 2; ++ks) {
            const uint32_t ko = bufo + (uint32_t)ks * 32;
            uint32_t ahi[4][4], alo[4][4], bb[2][4];
#pragma unroll
            for (int mi = 0; mi < 4; ++mi) {
                ldm_x4(ahi[mi], a_rel[mi] + ko);
                ldm_x4(alo[mi], a_rel[mi] + ko + PLANE);
            }
#pragma unroll
            for (int g = 0; g < 2; ++g) ldm_x4(bb[g], b_rel[g] + ko);         // B hi
#pragma unroll
            for (int mi = 0; mi < 4; ++mi)
#pragma unroll
                for (int ni = 0; ni < 4; ++ni)
                    mma_bf16(acc[mi][ni], ahi[mi], bb[ni >> 1][ni & 1], bb[ni >> 1][(ni & 1) + 2]);
#pragma unroll
            for (int mi = 0; mi < 4; ++mi)
#pragma unroll
                for (int ni = 0; ni < 4; ++ni)
                    mma_bf16(acc[mi][ni], alo[mi], bb[ni >> 1][ni & 1], bb[ni >> 1][(ni & 1) + 2]);
#pragma unroll
            for (int g = 0; g < 2; ++g) ldm_x4(bb[g], b_rel[g] + ko + PLANE); // B lo
#pragma unroll
            for (int mi = 0; mi < 4; ++mi)
#pragma unroll
                for (int ni = 0; ni < 4; ++ni)
                    mma_bf16(acc[mi][ni], ahi[mi], bb[ni >> 1][ni & 1], bb[ni >> 1][(ni & 1) + 2]);
        }
        __syncthreads();
    }

    // epilogue: distances into dbuf
#pragma unroll
    for (int mi = 0; mi < 4; ++mi) {
        int   r0  = wm * 64 + mi * 16 + (lane >> 2);
        float si0 = sqi[r0], si1 = sqi[r0 + 8];
#pragma unroll
        for (int ni = 0; ni < 4; ++ni) {
            int cl = wn * 32 + ni * 8 + 2 * (lane & 3);
            float sj0 = sqj[cl], sj1 = sqj[cl + 1];
            dbuf[r0 * DSTR + cl]           = si0 + sj0 - 2.f * acc[mi][ni][0];
            dbuf[r0 * DSTR + cl + 1]       = si0 + sj1 - 2.f * acc[mi][ni][1];
            dbuf[(r0 + 8) * DSTR + cl]     = si1 + sj0 - 2.f * acc[mi][ni][2];
            dbuf[(r0 + 8) * DSTR + cl + 1] = si1 + sj1 - 2.f * acc[mi][ni][3];
        }
    }
    __syncthreads();

    // concurrent scans with 4-wide batched-min filtering
    if (tid < TM) {
        float hp[K_NN];
        int   hx[K_NN];
#pragma unroll
        for (int t = 0; t < K_NN; ++t) { hp[t] = 3.4e38f; hx[t] = 0; }
        float w = 3.4e38f;
        const float4* drow = (const float4*)&dbuf[tid * DSTR];   // 528B rows: aligned
#pragma unroll 1
        for (int q = 0; q < TN / 4; ++q) {
            float4 v = drow[q];
            float m = fminf(fminf(v.x, v.y), fminf(v.z, v.w));
            if (m < w) {
                int jb = jt + 4 * q;
                ins1(v.x, jb,     hp, hx, w);
                ins1(v.y, jb + 1, hp, hx, w);
                ins1(v.z, jb + 2, hp, hx, w);
                ins1(v.w, jb + 3, hp, hx, w);
            }
        }
        size_t row = rowbase + i0 + tid;
#pragma unroll
        for (int t = 0; t < K_NN; ++t)
            g_pc[((size_t)tj * K_NN + t) * n_rows + row] = make_float2(hp[t], (float)hx[t]);
    } else if (ti != tj) {
        const int col = tid - TM;
        float hp[K_NN];
        int   hx[K_NN];
#pragma unroll
        for (int t = 0; t < K_NN; ++t) { hp[t] = 3.4e38f; hx[t] = 0; }
        float w = 3.4e38f;
#pragma unroll 1
        for (int q = 0; q < TM / 4; ++q) {
            float d0 = dbuf[(4 * q)     * DSTR + col];
            float d1 = dbuf[(4 * q + 1) * DSTR + col];
            float d2 = dbuf[(4 * q + 2) * DSTR + col];
            float d3 = dbuf[(4 * q + 3) * DSTR + col];
            float m = fminf(fminf(d0, d1), fminf(d2, d3));
            if (m < w) {
                int rb = i0 + 4 * q;
                ins1(d0, rb,     hp, hx, w);
                ins1(d1, rb + 1, hp, hx, w);
                ins1(d2, rb + 2, hp, hx, w);
                ins1(d3, rb + 3, hp, hx, w);
            }
        }
        size_t row = rowbase + jt + col;
#pragma unroll
        for (int t = 0; t < K_NN; ++t)
            g_pc[((size_t)ti * K_NN + t) * n_rows + row] = make_float2(hp[t], (float)hx[t]);
    }
}

// ---------------------------------------------------------------------------
__global__ void merge_kernel(float* __restrict__ out_d, float* __restrict__ out_s,
                             float* __restrict__ out_t,
                             int L, int NTJ, int write_idx, int n_rows) {
    int row = blockIdx.x * blockDim.x + threadIdx.x;
    if (row >= n_rows) return;
    float hp[K_NN];
    int   hx[K_NN];
#pragma unroll
    for (int t = 0; t < K_NN; ++t) { hp[t] = 3.4e38f; hx[t] = 0; }
    float w = 3.4e38f;
#pragma unroll 1
    for (int tj = 0; tj < NTJ; ++tj) {
#pragma unroll 1
        for (int t = 0; t < K_NN; ++t) {
            float2 c = g_pc[((size_t)tj * K_NN + t) * n_rows + row];
            float d = c.x;
            if (d >= w) break;              // list sorted ascending
            int jg = (int)c.y;
#pragma unroll
            for (int u = K_NN - 1; u >= 1; --u) {
                if (hp[u - 1] > d)  { hp[u] = hp[u - 1]; hx[u] = hx[u - 1]; }
                else if (hp[u] > d) { hp[u] = d;         hx[u] = jg; }
            }
            if (hp[0] > d)          { hp[0] = d;         hx[0] = jg; }
            w = hp[K_NN - 1];
        }
    }
    size_t rowbase = (size_t)(row / L) * L;
    float  srcv = (float)row;
    float* dd = out_d + (size_t)row * K_NN;
#pragma unroll
    for (int t = 0; t < K_NN; ++t) dd[t] = hp[t];
    if (write_idx) {
        float* ds = out_s + (size_t)row * K_NN;
        float* dt = out_t + (size_t)row * K_NN;
#pragma unroll
        for (int t = 0; t < K_NN; ++t) {
            ds[t] = srcv;
            dt[t] = (float)(rowbase + hx[t]);
        }
    }
}

// ---------------------------------------------------------------------------
extern "C" void kernel_launch(void* const* d_in, const int* in_sizes, int n_in,
                              void* d_out, int out_size) {
    const float* h = (const float*)d_in[0];
    int B = in_sizes[1];
    int n_rows = in_sizes[0] / D_DIM;
    int L = n_rows / B;
    int NTJ = L / TN;

    float* out_d = (float*)d_out;
    size_t Nd = (size_t)n_rows * K_NN;
    int three = (size_t)out_size >= 3 * Nd;
    float* out_s = three ? out_d + Nd : out_d;
    float* out_t = three ? out_d + 2 * Nd : out_d;

    cudaFuncSetAttribute(knn_part, cudaFuncAttributeMaxDynamicSharedMemorySize, SMEM_TOT);

    prep_kernel<<<(n_rows + 7) / 8, 256>>>(h, n_rows);
    dim3 grid(NTJ * (NTJ + 1) / 2, 1, B);
    knn_part<<<grid, THREADS, SMEM_TOT>>>(L, NTJ, n_rows);
    merge_kernel<<<(n_rows + 255) / 256, 256>>>(out_d, out_s, out_t, L, NTJ, three, n_rows);
}